// round 5
// baseline (speedup 1.0000x reference)
#include <cuda_runtime.h>

// RawISPProcessing: demosaic (2x bilinear; reference's flips cancel exactly) +
// fused channel-flip/awb/ccm 3x3 matrix (incl. the *2) + gamma, for pred & gt.
//
// R5: R4 rolling-window structure + forced occupancy (launch_bounds(128,12)
// -> <=40 regs, 75% occ) and finer block granularity for tail smoothing.

#define HIN  512
#define WIN  512
#define PLANE (HIN * WIN)
#define OPLANE (1024 * 1024)
#define R_ROWS 8

// 0.25*a + 0.75*b  (FADD + FFMA-imm form)
__device__ __forceinline__ float lerp14(float a, float b) {
    return fmaf(0.25f, a - b, b);
}

__device__ __forceinline__ float gamma_pow(float v) {
    v = fmaxf(v, 1e-8f);
    float l;
    asm("lg2.approx.f32 %0, %1;" : "=f"(l) : "f"(v));
    l *= 0.45454545454545453f;   // 1/2.2
    float r;
    asm("ex2.approx.f32 %0, %1;" : "=f"(r) : "f"(l));
    return r;
}

// Horizontal lerps of one input row, both output columns, all 4 planes.
struct HL { float r0, r1, gr0, gr1, gb0, gb1, b0, b1; };

__device__ __forceinline__ HL hlerp(const float* __restrict__ img, int row,
                                    int wm, int w, int wp) {
    const float* p = img + row * WIN;
    HL h;
    float a, b, c;
    a = p[wm];             b = p[w];             c = p[wp];
    h.r0 = lerp14(a, b);   h.r1 = lerp14(c, b);
    a = p[PLANE + wm];     b = p[PLANE + w];     c = p[PLANE + wp];
    h.gr0 = lerp14(a, b);  h.gr1 = lerp14(c, b);
    a = p[2 * PLANE + wm]; b = p[2 * PLANE + w]; c = p[2 * PLANE + wp];
    h.gb0 = lerp14(a, b);  h.gb1 = lerp14(c, b);
    a = p[3 * PLANE + wm]; b = p[3 * PLANE + w]; c = p[3 * PLANE + wp];
    h.b0 = lerp14(a, b);   h.b1 = lerp14(c, b);
    return h;
}

// Color matrix + gamma + store for one output row (2 cols x 3 channels).
__device__ __forceinline__ void emit_row(float* __restrict__ po, const float* A,
                                         float r0, float r1, float g0, float g1,
                                         float b0, float b1) {
#pragma unroll
    for (int c = 0; c < 3; c++) {
        float v0 = gamma_pow(fmaf(A[c], r0, fmaf(A[3 + c], g0, A[6 + c] * b0)));
        float v1 = gamma_pow(fmaf(A[c], r1, fmaf(A[3 + c], g1, A[6 + c] * b1)));
        *(float2*)(po + c * OPLANE) = make_float2(v0, v1);
    }
}

// Even output row: 0.25*ha + 0.75*hb.  G: even col = avg, odd = gr.
__device__ __forceinline__ void emit_even(float* __restrict__ po, const float* A,
                                          const HL& ha, const HL& hb) {
    float r0 = lerp14(ha.r0, hb.r0),   r1 = lerp14(ha.r1, hb.r1);
    float gr0 = lerp14(ha.gr0, hb.gr0), gr1 = lerp14(ha.gr1, hb.gr1);
    float gb0 = lerp14(ha.gb0, hb.gb0);
    float b0 = lerp14(ha.b0, hb.b0),   b1 = lerp14(ha.b1, hb.b1);
    emit_row(po, A, r0, r1, fmaf(0.5f, gr0 - gb0, gb0), gr1, b0, b1);
}

// Odd output row: 0.75*ha + 0.25*hb.  G: even col = gb, odd = avg.
__device__ __forceinline__ void emit_odd(float* __restrict__ po, const float* A,
                                         const HL& ha, const HL& hb) {
    float r0 = lerp14(hb.r0, ha.r0),   r1 = lerp14(hb.r1, ha.r1);
    float gr1 = lerp14(hb.gr1, ha.gr1);
    float gb0 = lerp14(hb.gb0, ha.gb0), gb1 = lerp14(hb.gb1, ha.gb1);
    float b0 = lerp14(hb.b0, ha.b0),   b1 = lerp14(hb.b1, ha.b1);
    emit_row(po, A, r0, r1, gb0, fmaf(0.5f, gr1 - gb1, gb1), b0, b1);
}

__global__ __launch_bounds__(128, 12)
void isp_kernel(const float* __restrict__ pred,
                const float* __restrict__ gt,
                const float* __restrict__ awb,
                const float* __restrict__ ccm,
                float* __restrict__ out) {
    const int w = blockIdx.x * 32 + threadIdx.x;     // input col 0..511
    const int strip = blockIdx.y * 4 + threadIdx.y;  // 0..63
    const int h0 = strip * R_ROWS;
    const int z = blockIdx.z;                        // which*8 + b
    const int b = z & 7;

    const float* __restrict__ img =
        ((z >> 3) ? gt : pred) + (size_t)b * (4 * PLANE);

    // fused matrix: A[j*3+c] = 2 * sum_m awb[b,2-j,m] * ccm[b,m,2-c]
    float A[9];
    {
        const float* Aw = awb + b * 9;
        const float* Cm = ccm + b * 9;
#pragma unroll
        for (int j = 0; j < 3; j++)
#pragma unroll
            for (int c = 0; c < 3; c++) {
                float s = 0.0f;
#pragma unroll
                for (int m = 0; m < 3; m++)
                    s = fmaf(__ldg(Aw + (2 - j) * 3 + m),
                             __ldg(Cm + m * 3 + (2 - c)), s);
                A[j * 3 + c] = 2.0f * s;
            }
    }

    const int wm = max(w - 1, 0);
    const int wp = min(w + 1, WIN - 1);

    float* po = out + (size_t)z * (3 * (size_t)OPLANE)
                    + (size_t)(2 * h0) * 1024 + 2 * w;

    HL ha = hlerp(img, max(h0 - 1, 0), wm, w, wp);
    HL hb = hlerp(img, h0, wm, w, wp);

    // first row of strip: output row 2*h0 (even) from (h0-1, h0)
    emit_even(po, A, ha, hb);
    po += 1024;

#pragma unroll 2
    for (int r = 0; r < R_ROWS - 1; r++) {
        ha = hb;
        hb = hlerp(img, h0 + r + 1, wm, w, wp);
        emit_odd(po, A, ha, hb);          // row 2*(h0+r)+1
        emit_even(po + 1024, A, ha, hb);  // row 2*(h0+r)+2
        po += 2048;
    }

    // last row of strip: output row 2*h0+2R-1 (odd) from (h0+R-1, h0+R)
    ha = hb;
    hb = hlerp(img, min(h0 + R_ROWS, HIN - 1), wm, w, wp);
    emit_odd(po, A, ha, hb);
}

extern "C" void kernel_launch(void* const* d_in, const int* in_sizes, int n_in,
                              void* d_out, int out_size) {
    const float* pred = (const float*)d_in[0];
    const float* gt   = (const float*)d_in[1];
    const float* awb  = (const float*)d_in[2];
    const float* ccm  = (const float*)d_in[3];
    // d_in[4] = rgb_gain: unused by the reference

    dim3 blk(32, 4);
    dim3 grd(16, 16, 16);   // 512 cols x 64 strips x (2 images * 8 batches)
    isp_kernel<<<grd, blk>>>(pred, gt, awb, ccm, (float*)d_out);
}

// round 6
// speedup vs baseline: 1.2391x; 1.2391x over previous
#include <cuda_runtime.h>

// RawISPProcessing: demosaic (2x bilinear; reference's flips cancel exactly) +
// fused channel-flip/awb/ccm 3x3 matrix (incl. the *2) + gamma, for pred & gt.
//
// R6: rolling vertical window (R4) x 2 input cols per thread -> 4 output
// cols, STG.128 streaming stores, shared h-lerp taps. No reg cap (R5 lesson).

#define HIN  512
#define WIN  512
#define PLANE (HIN * WIN)
#define OPLANE (1024 * 1024)
#define R_ROWS 4

// 0.25*a + 0.75*b  (FADD + FFMA-imm form)
__device__ __forceinline__ float lerp14(float a, float b) {
    return fmaf(0.25f, a - b, b);
}

__device__ __forceinline__ float gamma_pow(float v) {
    v = fmaxf(v, 1e-8f);
    float l;
    asm("lg2.approx.f32 %0, %1;" : "=f"(l) : "f"(v));
    l *= 0.45454545454545453f;   // 1/2.2
    float r;
    asm("ex2.approx.f32 %0, %1;" : "=f"(r) : "f"(l));
    return r;
}

// Horizontal lerps of one input row: 2 input cols -> 4 output cols x 4 planes.
// Layout: h[plane*4 + outcol]. Taps per plane: wm, w0, w0+1, wp2 (4 LDG).
struct HL { float v[16]; };

__device__ __forceinline__ HL hlerp(const float* __restrict__ img, int row,
                                    int wm, int w0, int wp2) {
    const float* p = img + row * WIN;
    HL h;
#pragma unroll
    for (int k = 0; k < 4; k++) {
        const float* q = p + k * PLANE;
        float t0 = q[wm], t1 = q[w0], t2 = q[w0 + 1], t3 = q[wp2];
        h.v[4 * k + 0] = lerp14(t0, t1);
        h.v[4 * k + 1] = lerp14(t2, t1);
        h.v[4 * k + 2] = lerp14(t1, t2);
        h.v[4 * k + 3] = lerp14(t3, t2);
    }
    return h;
}

// matvec + gamma + one streaming STG.128 per channel (4 output cols).
__device__ __forceinline__ void emit_row(float* __restrict__ po, const float* A,
                                         const float r[4], const float g[4],
                                         const float b[4]) {
#pragma unroll
    for (int c = 0; c < 3; c++) {
        float4 o;
        o.x = gamma_pow(fmaf(A[c], r[0], fmaf(A[3 + c], g[0], A[6 + c] * b[0])));
        o.y = gamma_pow(fmaf(A[c], r[1], fmaf(A[3 + c], g[1], A[6 + c] * b[1])));
        o.z = gamma_pow(fmaf(A[c], r[2], fmaf(A[3 + c], g[2], A[6 + c] * b[2])));
        o.w = gamma_pow(fmaf(A[c], r[3], fmaf(A[3 + c], g[3], A[6 + c] * b[3])));
        __stcs((float4*)(po + c * OPLANE), o);
    }
}

// Even output row: 0.25*ha + 0.75*hb.  G: even cols = avg(gr,gb), odd = gr.
__device__ __forceinline__ void emit_even(float* __restrict__ po, const float* A,
                                          const HL& ha, const HL& hb) {
    float r[4], g[4], b[4];
#pragma unroll
    for (int j = 0; j < 4; j++) r[j] = lerp14(ha.v[j], hb.v[j]);
#pragma unroll
    for (int j = 0; j < 4; j++) b[j] = lerp14(ha.v[12 + j], hb.v[12 + j]);
    float gr0 = lerp14(ha.v[4], hb.v[4]);
    float gr1 = lerp14(ha.v[5], hb.v[5]);
    float gr2 = lerp14(ha.v[6], hb.v[6]);
    float gr3 = lerp14(ha.v[7], hb.v[7]);
    float gb0 = lerp14(ha.v[8], hb.v[8]);
    float gb2 = lerp14(ha.v[10], hb.v[10]);
    g[0] = fmaf(0.5f, gr0 - gb0, gb0);
    g[1] = gr1;
    g[2] = fmaf(0.5f, gr2 - gb2, gb2);
    g[3] = gr3;
    emit_row(po, A, r, g, b);
}

// Odd output row: 0.75*ha + 0.25*hb.  G: even cols = gb, odd = avg(gr,gb).
__device__ __forceinline__ void emit_odd(float* __restrict__ po, const float* A,
                                         const HL& ha, const HL& hb) {
    float r[4], g[4], b[4];
#pragma unroll
    for (int j = 0; j < 4; j++) r[j] = lerp14(hb.v[j], ha.v[j]);
#pragma unroll
    for (int j = 0; j < 4; j++) b[j] = lerp14(hb.v[12 + j], ha.v[12 + j]);
    float gr1 = lerp14(hb.v[5], ha.v[5]);
    float gr3 = lerp14(hb.v[7], ha.v[7]);
    float gb0 = lerp14(hb.v[8], ha.v[8]);
    float gb1 = lerp14(hb.v[9], ha.v[9]);
    float gb2 = lerp14(hb.v[10], ha.v[10]);
    float gb3 = lerp14(hb.v[11], ha.v[11]);
    g[0] = gb0;
    g[1] = fmaf(0.5f, gr1 - gb1, gb1);
    g[2] = gb2;
    g[3] = fmaf(0.5f, gr3 - gb3, gb3);
    emit_row(po, A, r, g, b);
}

__global__ __launch_bounds__(128)
void isp_kernel(const float* __restrict__ pred,
                const float* __restrict__ gt,
                const float* __restrict__ awb,
                const float* __restrict__ ccm,
                float* __restrict__ out) {
    const int cp = blockIdx.x * 32 + threadIdx.x;    // col-pair 0..255
    const int w0 = 2 * cp;                           // input col base
    const int strip = blockIdx.y * 4 + threadIdx.y;  // 0..127
    const int h0 = strip * R_ROWS;
    const int z = blockIdx.z;                        // which*8 + b
    const int b = z & 7;

    const float* __restrict__ img =
        ((z >> 3) ? gt : pred) + (size_t)b * (4 * PLANE);

    // fused matrix: A[j*3+c] = 2 * sum_m awb[b,2-j,m] * ccm[b,m,2-c]
    float A[9];
    {
        const float* Aw = awb + b * 9;
        const float* Cm = ccm + b * 9;
#pragma unroll
        for (int j = 0; j < 3; j++)
#pragma unroll
            for (int c = 0; c < 3; c++) {
                float s = 0.0f;
#pragma unroll
                for (int m = 0; m < 3; m++)
                    s = fmaf(__ldg(Aw + (2 - j) * 3 + m),
                             __ldg(Cm + m * 3 + (2 - c)), s);
                A[j * 3 + c] = 2.0f * s;
            }
    }

    const int wm  = max(w0 - 1, 0);
    const int wp2 = min(w0 + 2, WIN - 1);

    float* po = out + (size_t)z * (3 * (size_t)OPLANE)
                    + (size_t)(2 * h0) * 1024 + 4 * cp;

    HL ha = hlerp(img, max(h0 - 1, 0), wm, w0, wp2);
    HL hb = hlerp(img, h0, wm, w0, wp2);

    // first row of strip: output row 2*h0 (even) from (h0-1, h0)
    emit_even(po, A, ha, hb);
    po += 1024;

#pragma unroll
    for (int r = 0; r < R_ROWS - 1; r++) {
        ha = hb;
        hb = hlerp(img, h0 + r + 1, wm, w0, wp2);
        emit_odd(po, A, ha, hb);          // row 2*(h0+r)+1
        emit_even(po + 1024, A, ha, hb);  // row 2*(h0+r)+2
        po += 2048;
    }

    // last row of strip: output row 2*h0+2R-1 (odd) from (h0+R-1, h0+R)
    ha = hb;
    hb = hlerp(img, min(h0 + R_ROWS, HIN - 1), wm, w0, wp2);
    emit_odd(po, A, ha, hb);
}

extern "C" void kernel_launch(void* const* d_in, const int* in_sizes, int n_in,
                              void* d_out, int out_size) {
    const float* pred = (const float*)d_in[0];
    const float* gt   = (const float*)d_in[1];
    const float* awb  = (const float*)d_in[2];
    const float* ccm  = (const float*)d_in[3];
    // d_in[4] = rgb_gain: unused by the reference

    dim3 blk(32, 4);
    dim3 grd(8, 32, 16);   // 256 col-pairs x 128 strips x (2 images * 8 batches)
    isp_kernel<<<grd, blk>>>(pred, gt, awb, ccm, (float*)d_out);
}